// round 5
// baseline (speedup 1.0000x reference)
#include <cuda_runtime.h>

// dct: [16, 64, 256, 256] fp32, mean/std: [64] fp32, out: [16, 1, 2048, 2048] fp32
#define HW      65536        // 256*256
#define OUTW    2048

__global__ __launch_bounds__(256, 4) void idct_kernel(
    const float* __restrict__ dct,
    const float* __restrict__ mean_,
    const float* __restrict__ std_,
    float* __restrict__ out)
{
    // s_hx[u][xp] = 0.5*c_u*cos((2*xp+1)u*pi/16)            (xp = 0..3, butterfly)
    // s_hy[v][yp] = 0.5*c_v*cos((2*yp+1)v*pi/16) / 255      (yp = 0..3)
    __shared__ float s_hx[8][4];
    __shared__ float s_hy[8][4];
    __shared__ float s_std[64];
    __shared__ float s_mean[64];

    int tid = threadIdx.x;
    if (tid < 64) {
        int u = tid >> 3, x = tid & 7;
        float c = (u == 0) ? 0.70710678118654752440f : 1.0f;
        float h = cospif((float)((2 * x + 1) * u) * (1.0f / 16.0f));
        float v = 0.5f * c * h;
        if (x < 4) {
            s_hx[u][x] = v;
            s_hy[u][x] = v * (1.0f / 255.0f);
        }
        s_std[tid]  = std_[tid];
        s_mean[tid] = mean_[tid];
    }
    __syncthreads();

    // Two threads per 8x8 block: even lane accumulates even-u (E) terms,
    // odd lane odd-u (O) terms. rows xp = E+O, rows 7-xp = E-O.
    int parity = tid & 1;
    unsigned gp  = blockIdx.x * 128u + ((unsigned)tid >> 1);  // block index 0..1M-1
    unsigned b   = gp >> 16;
    unsigned pos = gp & 65535u;                               // h*256 + w
    const float* src = dct + (size_t)b * 64u * HW + pos + (size_t)(parity * 8) * HW;

    const float K = 128.0f / 255.0f;      // folded into E (even-lane) accumulator
    float init = parity ? 0.0f : K;
    float acc[4][8];
    #pragma unroll
    for (int xp = 0; xp < 4; xp++)
        #pragma unroll
        for (int y = 0; y < 8; y++) acc[xp][y] = init;

    #pragma unroll
    for (int up = 0; up < 4; up++) {
        // channels: (2*up + parity)*8 + v ; src already offset by parity*8*HW
        int cbase = up * 16 + parity * 8;
        float t[8];
        #pragma unroll
        for (int v = 0; v < 8; v++)
            t[v] = __ldg(src + (size_t)(up * 16 + v) * HW);
        #pragma unroll
        for (int v = 0; v < 8; v++)
            t[v] = fmaf(t[v], s_std[cbase + v], s_mean[cbase + v]);

        // y-pass (v -> y) with even/odd-v butterfly
        float gy[8];
        #pragma unroll
        for (int yp = 0; yp < 4; yp++) {
            float te = 0.0f, to = 0.0f;
            #pragma unroll
            for (int vp = 0; vp < 4; vp++) {
                te = fmaf(s_hy[2 * vp    ][yp], t[2 * vp    ], te);
                to = fmaf(s_hy[2 * vp + 1][yp], t[2 * vp + 1], to);
            }
            gy[yp]     = te + to;
            gy[7 - yp] = te - to;
        }

        // x-pass partial accumulation for this thread's parity set
        #pragma unroll
        for (int xp = 0; xp < 4; xp++) {
            float w = s_hx[2 * up + parity][xp];
            #pragma unroll
            for (int y = 0; y < 8; y++)
                acc[xp][y] = fmaf(w, gy[y], acc[xp][y]);
        }
    }

    // Pair exchange + write: even lane writes rows 0..3 (E+O),
    // odd lane writes rows 7..4 (E-O = Q-P for odd lane).
    unsigned hh = pos >> 8, ww = pos & 255u;
    float* dst = out + (size_t)b * ((size_t)OUTW * OUTW)
                     + (size_t)hh * 8 * OUTW + (size_t)ww * 8;

    #pragma unroll
    for (int xp = 0; xp < 4; xp++) {
        float r[8];
        #pragma unroll
        for (int y = 0; y < 8; y++) {
            float q = __shfl_xor_sync(0xffffffffu, acc[xp][y], 1);
            r[y] = parity ? (q - acc[xp][y]) : (acc[xp][y] + q);
        }
        int row = parity ? (7 - xp) : xp;
        float4 a, bq;
        a.x  = r[0]; a.y  = r[1]; a.z  = r[2]; a.w  = r[3];
        bq.x = r[4]; bq.y = r[5]; bq.z = r[6]; bq.w = r[7];
        *(float4*)(dst + (size_t)row * OUTW)     = a;
        *(float4*)(dst + (size_t)row * OUTW + 4) = bq;
    }
}

extern "C" void kernel_launch(void* const* d_in, const int* in_sizes, int n_in,
                              void* d_out, int out_size)
{
    (void)in_sizes; (void)n_in; (void)out_size;
    const float* dct   = (const float*)d_in[0];
    const float* mean_ = (const float*)d_in[1];
    const float* std_  = (const float*)d_in[2];
    float* out = (float*)d_out;
    // 1,048,576 8x8 blocks, 2 threads per block -> 128 blocks per 256-thr CTA.
    idct_kernel<<<8192, 256>>>(dct, mean_, std_, out);
}

// round 6
// speedup vs baseline: 1.6063x; 1.6063x over previous
#include <cuda_runtime.h>

// dct: [16, 64, 256, 256] fp32, mean/std: [64] fp32, out: [16, 1, 2048, 2048] fp32
#define HW      65536        // 256*256
#define OUTW    2048

__global__ __launch_bounds__(256, 2) void idct_kernel(
    const float* __restrict__ dct,
    const float* __restrict__ mean_,
    const float* __restrict__ std_,
    float* __restrict__ out)
{
    // s_hx[u][xp] = 0.5*c_u*cos((2*xp+1)u*pi/16)            (xp = 0..3, butterfly)
    // s_hy[v][yp] = 0.5*c_v*cos((2*yp+1)v*pi/16) / 255      (yp = 0..3)
    __shared__ float s_hx[8][8];   // full x table (used per-u)
    __shared__ float s_hy[8][4];
    __shared__ float s_std[64];
    __shared__ float s_mean[64];

    int tid = threadIdx.x;
    if (tid < 64) {
        int u = tid >> 3, x = tid & 7;
        float c = (u == 0) ? 0.70710678118654752440f : 1.0f;
        float h = cospif((float)((2 * x + 1) * u) * (1.0f / 16.0f));
        float v = 0.5f * c * h;
        s_hx[u][x] = v;
        if (x < 4) s_hy[u][x] = v * (1.0f / 255.0f);
        s_std[tid]  = std_[tid];
        s_mean[tid] = mean_[tid];
    }
    __syncthreads();

    unsigned gid = blockIdx.x * 256u + (unsigned)tid;   // 0 .. 16*65536-1
    unsigned b   = gid >> 16;
    unsigned pos = gid & 65535u;                         // h*256 + w
    const float* src = dct + (size_t)b * 64u * HW + pos;

    // x-pass accumulators: rows xp = E+O, rows 7-xp = E-O. K folded into E.
    const float K = 128.0f / 255.0f;
    float E[4][8], O[4][8];
    #pragma unroll
    for (int xp = 0; xp < 4; xp++)
        #pragma unroll
        for (int y = 0; y < 8; y++) { E[xp][y] = K; O[xp][y] = 0.0f; }

    // Process two u's per iteration: 16 front-batched LDGs -> 32KB/SM in flight
    #pragma unroll
    for (int uu = 0; uu < 8; uu += 2) {
        float t[16];
        #pragma unroll
        for (int k = 0; k < 16; k++)
            t[k] = __ldg(src + (size_t)(uu * 8 + k) * HW);
        #pragma unroll
        for (int k = 0; k < 16; k++)
            t[k] = fmaf(t[k], s_std[uu * 8 + k], s_mean[uu * 8 + k]);

        #pragma unroll
        for (int j = 0; j < 2; j++) {
            int u = uu + j;
            float* tu = &t[j * 8];

            // y-pass with even/odd v butterfly
            float te[4] = {0.f,0.f,0.f,0.f}, to[4] = {0.f,0.f,0.f,0.f};
            #pragma unroll
            for (int vp = 0; vp < 4; vp++) {
                #pragma unroll
                for (int yp = 0; yp < 4; yp++) {
                    te[yp] = fmaf(s_hy[2*vp    ][yp], tu[2*vp    ], te[yp]);
                    to[yp] = fmaf(s_hy[2*vp + 1][yp], tu[2*vp + 1], to[yp]);
                }
            }
            float ty[8];
            #pragma unroll
            for (int yp = 0; yp < 4; yp++) {
                ty[yp]     = te[yp] + to[yp];
                ty[7 - yp] = te[yp] - to[yp];
            }

            // x-pass: even u -> E, odd u -> O (compile-time branch on j parity)
            #pragma unroll
            for (int xp = 0; xp < 4; xp++) {
                float w = s_hx[u][xp];
                if ((u & 1) == 0) {
                    #pragma unroll
                    for (int y = 0; y < 8; y++) E[xp][y] = fmaf(w, ty[y], E[xp][y]);
                } else {
                    #pragma unroll
                    for (int y = 0; y < 8; y++) O[xp][y] = fmaf(w, ty[y], O[xp][y]);
                }
            }
        }
    }

    // Write 8x8 pixel block: two STG.128 per row.
    unsigned hh = pos >> 8, ww = pos & 255u;
    float* dst = out + (size_t)b * ((size_t)OUTW * OUTW)
                     + (size_t)hh * 8 * OUTW + (size_t)ww * 8;

    #pragma unroll
    for (int xp = 0; xp < 4; xp++) {
        float4 a, bq;
        a.x  = E[xp][0] + O[xp][0];  a.y  = E[xp][1] + O[xp][1];
        a.z  = E[xp][2] + O[xp][2];  a.w  = E[xp][3] + O[xp][3];
        bq.x = E[xp][4] + O[xp][4];  bq.y = E[xp][5] + O[xp][5];
        bq.z = E[xp][6] + O[xp][6];  bq.w = E[xp][7] + O[xp][7];
        *(float4*)(dst + (size_t)xp * OUTW)     = a;
        *(float4*)(dst + (size_t)xp * OUTW + 4) = bq;

        float4 c4, d4;
        c4.x = E[xp][0] - O[xp][0];  c4.y = E[xp][1] - O[xp][1];
        c4.z = E[xp][2] - O[xp][2];  c4.w = E[xp][3] - O[xp][3];
        d4.x = E[xp][4] - O[xp][4];  d4.y = E[xp][5] - O[xp][5];
        d4.z = E[xp][6] - O[xp][6];  d4.w = E[xp][7] - O[xp][7];
        *(float4*)(dst + (size_t)(7 - xp) * OUTW)     = c4;
        *(float4*)(dst + (size_t)(7 - xp) * OUTW + 4) = d4;
    }
}

extern "C" void kernel_launch(void* const* d_in, const int* in_sizes, int n_in,
                              void* d_out, int out_size)
{
    (void)in_sizes; (void)n_in; (void)out_size;
    const float* dct   = (const float*)d_in[0];
    const float* mean_ = (const float*)d_in[1];
    const float* std_  = (const float*)d_in[2];
    float* out = (float*)d_out;
    // 16*256*256 = 1,048,576 blocks of 8x8 pixels, 1 thread each.
    idct_kernel<<<4096, 256>>>(dct, mean_, std_, out);
}